// round 17
// baseline (speedup 1.0000x reference)
#include <cuda_runtime.h>
#include <cuda_fp16.h>
#include <stdint.h>

#define BATCH 32
#define CIN   128
#define HH    56
#define WW    56
#define COUT  256
#define HP    58
#define NPIX  (HH*WW)            // 3136
#define IMGB  (HP*HP*CIN)        // padded image elements

// ---------------- scratch (device globals) ----------------------------------
__device__ __half g_qx[BATCH*HP*HP*CIN];   // padded NHWC, quantized ints as fp16
// B pre-fragmented: [chunk=tap*2+kh2][cohalf][8192 fp16] (16KB per sub-chunk)
__device__ __half g_qw[18*2*8192];
__device__ float  g_px[1024];
__device__ float  g_pw[64];
__device__ float  g_scale_x, g_dq;

// ---------------- helpers -----------------------------------------------------
__device__ __forceinline__ uint32_t smem_u32(const void* p) {
    uint32_t a;
    asm("{ .reg .u64 t; cvta.to.shared.u64 t, %1; cvt.u32.u64 %0, t; }" : "=r"(a) : "l"(p));
    return a;
}
#define SW128(o) ((o) ^ (((o) >> 3) & 0x70))

__device__ __forceinline__ void cp16(uint32_t dst, const void* src) {
    asm volatile("cp.async.cg.shared.global [%0], [%1], 16;" :: "r"(dst), "l"(src) : "memory");
}
#define CP_COMMIT()  asm volatile("cp.async.commit_group;" ::: "memory")
#define CP_WAIT(n)   asm volatile("cp.async.wait_group %0;" :: "n"(n) : "memory")

__device__ __forceinline__ unsigned lds32(uint32_t a) {
    unsigned v; asm volatile("ld.shared.b32 %0, [%1];" : "=r"(v) : "r"(a)); return v;
}

// fp16 HMMA: m16n8k16, A row-major, B col-major, f32 accumulate
__device__ __forceinline__ void hmma16816(float* d, const unsigned* a, const unsigned* b) {
    asm volatile("mma.sync.aligned.m16n8k16.row.col.f32.f16.f16.f32 "
        "{%0,%1,%2,%3}, {%4,%5,%6,%7}, {%8,%9}, {%0,%1,%2,%3};"
        : "+f"(d[0]), "+f"(d[1]), "+f"(d[2]), "+f"(d[3])
        : "r"(a[0]), "r"(a[1]), "r"(a[2]), "r"(a[3]), "r"(b[0]), "r"(b[1]));
}

__device__ __forceinline__ float warp_red_max(float m) {
    #pragma unroll
    for (int o = 16; o; o >>= 1) m = fmaxf(m, __shfl_xor_sync(0xffffffffu, m, o));
    return m;
}

// ---------------- 0: partial amax --------------------------------------------
__global__ void k_part(const float4* __restrict__ x, const float4* __restrict__ w) {
    int blk = blockIdx.x;
    const float4* p; int n4, stride, start;
    if (blk < 1024) { p = x; n4 = BATCH*CIN*HH*WW/4; start = blk*256 + threadIdx.x; stride = 1024*256; }
    else            { p = w; n4 = COUT*CIN*9/4;      start = (blk-1024)*256 + threadIdx.x; stride = 64*256; }
    float m = 0.f;
    for (int i = start; i < n4; i += stride) {
        float4 v = p[i];
        m = fmaxf(m, fmaxf(fmaxf(fabsf(v.x), fabsf(v.y)), fmaxf(fabsf(v.z), fabsf(v.w))));
    }
    m = warp_red_max(m);
    __shared__ float sm[8];
    int lane = threadIdx.x & 31, wid = threadIdx.x >> 5;
    if (lane == 0) sm[wid] = m;
    __syncthreads();
    if (wid == 0) {
        m = (lane < 8) ? sm[lane] : 0.f;
        m = warp_red_max(m);
        if (lane == 0) { if (blk < 1024) g_px[blk] = m; else g_pw[blk-1024] = m; }
    }
}

// ---------------- 1: finalize scales + quantize weights into FRAGMENT layout --
// g_qw element index o: sub = o>>13, f = o&8191; nc = sub>>1, cohalf = sub&1.
// f = (((wn*4+ks)*4 + j)*32 + lane)*8 + e
// co = cohalf*128 + wn*64 + j*16 + (lane>>2) + ((e&4)?8:0)
// ci = (nc&1)*64 + ks*16 + ((e>>1)&1)*8 + (lane&3)*2 + (e&1)
__global__ void k_quant_w(const float* __restrict__ wt) {
    __shared__ float s_sw;
    {
        float mx = 0.f, mw = 0.f;
        for (int i = threadIdx.x; i < 1024; i += blockDim.x) mx = fmaxf(mx, g_px[i]);
        if (threadIdx.x < 64) mw = g_pw[threadIdx.x];
        mx = warp_red_max(mx); mw = warp_red_max(mw);
        __shared__ float smx[8], smw[8];
        int lane = threadIdx.x & 31, wid = threadIdx.x >> 5;
        if (lane == 0) { smx[wid] = mx; smw[wid] = mw; }
        __syncthreads();
        if (threadIdx.x == 0) {
            float ax = 0.f, aw = 0.f;
            #pragma unroll
            for (int i = 0; i < 8; i++) { ax = fmaxf(ax, smx[i]); aw = fmaxf(aw, smw[i]); }
            float sx = __fdiv_rn(127.0f, ax);
            float sw = __fdiv_rn(127.0f, aw);
            s_sw = sw;
            if (blockIdx.x == 0) {
                g_scale_x = sx;
                g_dq = __fdiv_rn(1.0f, __fmul_rn(sx, sw));
            }
        }
        __syncthreads();
    }
    float sc = s_sw;
    const int n = 18*2*8192;
    for (int o = blockIdx.x*blockDim.x + threadIdx.x; o < n; o += gridDim.x*blockDim.x) {
        int f = o & 8191, sub = o >> 13;
        int nc = sub >> 1, cohalf = sub & 1;
        int tap = nc >> 1, kh2 = nc & 1;
        int e = f & 7, lane = (f >> 3) & 31;
        int j = (f >> 8) & 3, ks = (f >> 10) & 3, wn = (f >> 12) & 1;
        int co = cohalf*128 + wn*64 + j*16 + (lane >> 2) + ((e & 4) ? 8 : 0);
        int ci = kh2*64 + ks*16 + ((e >> 1) & 1)*8 + (lane & 3)*2 + (e & 1);
        float q = rintf(wt[(co*CIN + ci)*9 + tap] * sc);
        q = fminf(fmaxf(q, -127.f), 127.f);
        g_qw[o] = __float2half_rn(q);
    }
}

// ---------------- 2: quantize x into padded NHWC (store fp16) -----------------
__global__ void k_quant_x(const float* __restrict__ x) {
    int b = blockIdx.x / HP, hp = blockIdx.x % HP;
    __half* dst = g_qx + ((size_t)b*HP + hp)*HP*CIN;
    if (hp == 0 || hp == HP-1) {
        for (int e = threadIdx.x; e < HP*CIN/8; e += blockDim.x)
            ((int4*)dst)[e] = make_int4(0,0,0,0);
        return;
    }
    int h = hp - 1;
    __shared__ __half s[CIN][60];
    float sc = g_scale_x;
    const float* base = x + ((size_t)b*CIN*HH + h)*WW;
    for (int e = threadIdx.x; e < CIN*WW; e += blockDim.x) {
        int c = e / WW, w = e - c*WW;
        float q = rintf(base[(size_t)c*HH*WW + w] * sc);
        q = fminf(fmaxf(q, -127.f), 127.f);
        s[c][w] = __float2half_rn(q);
    }
    __syncthreads();
    for (int e = threadIdx.x; e < HP*CIN; e += blockDim.x) {
        int wp = e >> 7, c = e & 127;
        dst[e] = (wp == 0 || wp == HP-1) ? __float2half_rn(0.f) : s[c][wp-1];
    }
}

// ---------------- 3: fp16 HMMA conv — full-tap chunks, af+B reg pipelines -----
// CTA: 128 px x 128 co, 256 thr = 8 warps (4m x 2n); warp tile 32px x 64co.
// 9 chunks of 128 ci (one tap). Stage 32KB = [kh2][128px][64ci] (two SW128
// halves). 3 stages, prefetch dist 2, ONE sync/chunk (9 total).
// A fragments (af) double-buffered one (ks,mt)-block ahead in regs.
// B fragments LDG'd from fragment-layout gmem, double-buffered one k16 ahead.
#define STAGE 32768
#define SMEM_TOTAL (3*STAGE)

__global__ void __launch_bounds__(256, 2) k_conv(const float* __restrict__ bias,
                                                 float* __restrict__ out) {
    extern __shared__ char smem[];
    uint32_t sb = smem_u32(smem);
    float* s_out = (float*)smem;

    int tid = threadIdx.x;
    int wid = tid >> 5, lane = tid & 31;
    int wm = wid & 3, wn = wid >> 2;            // 4 x 2 warp grid
    int g = lane >> 2, tg = lane & 3;

    int tile   = blockIdx.x;                    // 0..24
    int cohalf = blockIdx.y;                    // 0 or 1
    int coBase = cohalf << 7;
    int bimg   = blockIdx.z;
    int p0 = tile * 128;

    // A producer: thread t -> row r=t>>1, 4x16B per half at (t&1)*4 (SW128)
    int r = tid >> 1, s4 = (tid & 1) << 2;
    int p = min(p0 + r, NPIX-1);
    int ph = p / WW, pw = p - ph*WW;
    const __half* qb = g_qx + (size_t)bimg * IMGB;
    const __half* abase = qb + (ph*HP + pw)*CIN;
    uint32_t dA[4];
    #pragma unroll
    for (int i = 0; i < 4; i++) dA[i] = SW128((uint32_t)(r*128 + (s4+i)*16));

    // B per-warp fragment pointer (int4 units): idx = nc*2048 + nks*128 + j*32
    const int4* bbase = (const int4*)g_qw + cohalf*1024 + wn*512 + lane;

    float acc[2][8][4];
    #pragma unroll
    for (int mt = 0; mt < 2; mt++)
        #pragma unroll
        for (int nt = 0; nt < 8; nt++)
            #pragma unroll
            for (int q = 0; q < 4; q++) acc[mt][nt][q] = 0.f;

    // ---- prefetch A chunks (taps) 0 and 1 ----
    #pragma unroll
    for (int pc = 0; pc < 2; pc++) {
        int dh = pc / 3, dw = pc - dh*3;        // pc<2 so dh=0
        const __half* as = abase + (dh*HP + dw)*CIN;
        uint32_t stg = sb + pc*STAGE;
        #pragma unroll
        for (int i = 0; i < 4; i++) {
            cp16(stg + dA[i],          as + (s4+i)*8);        // ci 0..63
            cp16(stg + 16384 + dA[i],  as + 64 + (s4+i)*8);   // ci 64..127
        }
        CP_COMMIT();
    }

    // ---- prefetch B fragments for global k16-step 0 ----
    int4 bfr[2][4];
    #pragma unroll
    for (int j = 0; j < 4; j++) bfr[0][j] = __ldg(bbase + j*32);

    for (int tap = 0; tap < 9; tap++) {
        if (tap < 8) { CP_WAIT(1); } else { CP_WAIT(0); }
        __syncthreads();

        // prefetch A chunk tap+2 into stage (tap+2)%3
        if (tap + 2 < 9) {
            int nt2 = tap + 2;
            int dh = nt2 / 3, dw = nt2 - dh*3;
            const __half* as = abase + (dh*HP + dw)*CIN;
            uint32_t stg = sb + (nt2 % 3)*STAGE;
            #pragma unroll
            for (int i = 0; i < 4; i++) {
                cp16(stg + dA[i],         as + (s4+i)*8);
                cp16(stg + 16384 + dA[i], as + 64 + (s4+i)*8);
            }
            CP_COMMIT();
        }

        uint32_t stgA = sb + (tap % 3)*STAGE;
        unsigned af[2][4];
        // preload af block 0 (ks=0, mt=0)
        {
            uint32_t base = (wm*32 + g)*128 + tg*4;
            af[0][0] = lds32(stgA + SW128(base));
            af[0][1] = lds32(stgA + SW128(base + 1024));
            af[0][2] = lds32(stgA + SW128(base + 16));
            af[0][3] = lds32(stgA + SW128(base + 1024 + 16));
        }

        #pragma unroll
        for (int blk = 0; blk < 16; blk++) {    // blk = ks*2 + mt, ks 0..7
            int ks = blk >> 1, mt = blk & 1;
            // prefetch next af block (within chunk)
            if (blk < 15) {
                int nb = blk + 1, nks = nb >> 1, nmt = nb & 1;
                uint32_t half = (uint32_t)(nks >> 2) * 16384;
                uint32_t base = (uint32_t)((wm*32 + nmt*16 + g)*128 + (nks & 3)*32 + tg*4);
                unsigned* d = af[nb & 1];
                d[0] = lds32(stgA + half + SW128(base));
                d[1] = lds32(stgA + half + SW128(base + 1024));
                d[2] = lds32(stgA + half + SW128(base + 16));
                d[3] = lds32(stgA + half + SW128(base + 1024 + 16));
            }
            // prefetch next B k16-step at start of each ks (mt==0)
            if (mt == 0) {
                int kb1 = tap*8 + ks + 1;
                if (kb1 < 72) {
                    int nc2 = kb1 >> 2, nks2 = kb1 & 3;
                    #pragma unroll
                    for (int j = 0; j < 4; j++)
                        bfr[(ks + 1) & 1][j] = __ldg(bbase + nc2*2048 + nks2*128 + j*32);
                }
            }
            const unsigned* bfp = (const unsigned*)&bfr[ks & 1][0];
            const unsigned* afp = af[blk & 1];
            #pragma unroll
            for (int j = 0; j < 4; j++) {
                hmma16816(acc[mt][2*j],     afp, bfp + j*4);
                hmma16816(acc[mt][2*j + 1], afp, bfp + j*4 + 2);
            }
        }
        // no bottom sync: next iteration's top sync orders stage reuse
    }
    __syncthreads();   // protect s_out overlay of stage smem

    // ---- epilogue: stage [64co][132px] in smem, coalesced dequant+bias stores
    float dq = g_dq;
    int rro = tid >> 7;             // 0..1
    int px = tid & 127;
    bool pv = (p0 + px) < NPIX;
    float* obase = out + ((size_t)bimg*COUT + coBase)*NPIX + p0 + px;

    #pragma unroll
    for (int pass = 0; pass < 2; pass++) {
        if (wn == pass) {
            #pragma unroll
            for (int mt = 0; mt < 2; mt++) {
                int px0 = wm*32 + mt*16 + g;
                #pragma unroll
                for (int nt = 0; nt < 8; nt++) {
                    int cl = nt*8 + tg*2;
                    s_out[cl*132 + px0]         = acc[mt][nt][0] * dq;
                    s_out[(cl+1)*132 + px0]     = acc[mt][nt][1] * dq;
                    s_out[cl*132 + px0 + 8]     = acc[mt][nt][2] * dq;
                    s_out[(cl+1)*132 + px0 + 8] = acc[mt][nt][3] * dq;
                }
            }
        }
        __syncthreads();
        if (pv) {
            #pragma unroll 8
            for (int it = 0; it < 32; it++) {
                int row = it*2 + rro;
                int co = pass*64 + row;
                obase[(size_t)co * NPIX] = s_out[row*132 + px] + __ldg(&bias[coBase + co]);
            }
        }
        __syncthreads();
    }
}

// ---------------- launch ------------------------------------------------------
extern "C" void kernel_launch(void* const* d_in, const int* in_sizes, int n_in,
                              void* d_out, int out_size) {
    const float* x    = (const float*)d_in[0];
    const float* wt   = (const float*)d_in[1];
    const float* bias = (const float*)d_in[2];
    float* out = (float*)d_out;

    cudaFuncSetAttribute(k_conv, cudaFuncAttributeMaxDynamicSharedMemorySize, SMEM_TOTAL);

    k_part<<<1088, 256>>>((const float4*)x, (const float4*)wt);   // idx 0
    k_quant_w<<<288, 256>>>(wt);                                  // idx 1
    k_quant_x<<<BATCH*HP, 256>>>(x);                              // idx 2
    dim3 grid(25, 2, BATCH);
    k_conv<<<grid, 256, SMEM_TOTAL>>>(bias, out);                 // idx 3 (ncu)
    (void)in_sizes; (void)n_in; (void)out_size;
}